// round 5
// baseline (speedup 1.0000x reference)
#include <cuda_runtime.h>
#include <cuda_bf16.h>
#include <cuda_fp16.h>
#include <cstdint>
#include <math.h>

#define NN   50000
#define EE   300000
#define FIN  16
#define FE   8
#define HH   64
#define HEADS 4
#define NGRP 64
#define KK   1024
#define E2   (EE + NN)
#define NPART 512
#define CHUNKS 16
#define CK   64               // k per chunk
#define G    16               // src nodes per block
#define NBLK (NN / G)         // 3125
#define MAXE 192              // edges per sweep (Poisson(96) -> ~10 sigma)
#define JMAX (MAXE / 16)      // 12 edges per warp max

// ---------------- scratch ----------------
static __device__ int   g_cnt[NN];
static __device__ int   g_ptr[NN + 1];
static __device__ int   g_cursor[NN];
static __device__ int   g_eperm[EE];
static __device__ int   g_deg[NN];
static __device__ float g_agg[NN * HH];
static __device__ float g_h[NN * HH];
static __device__ float g_xh[NN * HH];
static __device__ float g_asrc[NN * HEADS];
static __device__ float g_adst[NN * HEADS];
static __device__ float g_amax[NN * HEADS];
static __device__ float g_asum[NN * HEADS];
static __device__ float g_alpha[(size_t)E2 * HEADS];
static __device__ float g_gout[NN * HH];
static __device__ float g_h2[NN * HH];
static __device__ float g_pool[NGRP * HH];
static __device__ int   g_gcnt[NGRP];
static __device__ float g_psum[NPART];
static __device__ float g_psumsq[NPART];
static __device__ float g_stats[4];

__device__ __forceinline__ void atomicMaxF(float* addr, float v) {
    if (v >= 0.0f) atomicMax((int*)addr, __float_as_int(v));
    else           atomicMin((unsigned int*)addr, __float_as_uint(v));
}

__device__ __forceinline__ void cp16(uint32_t dst_s, const void* src_g) {
    asm volatile("cp.async.cg.shared.global [%0], [%1], 16;\n"
                 :: "r"(dst_s), "l"(src_g));
}

// ---------------- init / CSR ----------------
__global__ void k_init() {
    int i = blockIdx.x * blockDim.x + threadIdx.x;
    if (i < NN * HH) { g_agg[i] = 0.f; g_gout[i] = 0.f; }
    if (i < NN)      { g_cnt[i] = 0;   g_deg[i] = 0; }
    if (i < NN * HEADS) { g_amax[i] = -1e30f; g_asum[i] = 0.f; }
    if (i < NGRP * HH) g_pool[i] = 0.f;
    if (i < NGRP)      g_gcnt[i] = 0;
}

__global__ void k_hist(const int* __restrict__ ei) {
    int e = blockIdx.x * blockDim.x + threadIdx.x;
    if (e >= EE) return;
    atomicAdd(&g_cnt[ei[e]], 1);
    atomicAdd(&g_deg[ei[EE + e]], 1);
}

__global__ void k_scan() {
    __shared__ int ss[1024];
    const int CH = (NN + 1023) / 1024;
    int t = threadIdx.x;
    int lo = t * CH;
    int hi = lo + CH; if (hi > NN) hi = NN;
    int s = 0;
    for (int i = lo; i < hi; i++) s += g_cnt[i];
    ss[t] = s;
    __syncthreads();
    for (int off = 1; off < 1024; off <<= 1) {
        int v = (t >= off) ? ss[t - off] : 0;
        __syncthreads();
        ss[t] += v;
        __syncthreads();
    }
    int run = ss[t] - s;
    for (int i = lo; i < hi; i++) {
        g_ptr[i] = run;
        g_cursor[i] = run;
        run += g_cnt[i];
    }
    if (t == 0) g_ptr[NN] = EE;
}

__global__ void k_scatter(const int* __restrict__ ei) {
    int e = blockIdx.x * blockDim.x + threadIdx.x;
    if (e >= EE) return;
    int pos = atomicAdd(&g_cursor[ei[e]], 1);
    g_eperm[pos] = e;
}

// ---------------- fused NNConv message kernel ----------------
// Block owns G=16 src nodes + their (contiguous) CSR edge range.
// Per 64-k chunk: build Q chunk in SMEM (fp16) from W2 streamed via cp.async,
// then contract per-edge r (from SMEM W1 slice) against it.
// msg[e,h] = sum_k relu(ea@W1+b1)[k] * Q[src][k,h];  + bx[src][h] at the end.

// dynamic SMEM layout (bytes):
#define SM_QBUF   0                                    // G*64*32 half2 = 131072
#define SM_W2     (SM_QBUF + G * CK * 32 * 4)          // 2*8*1024 f32 = 65536
#define SM_BX     (SM_W2 + 2 * 8 * 1024 * 4)           // G*64 f32 = 4096
#define SM_XS2    (SM_BX + G * HH * 4)                 // G*16 float2 = 2048
#define SM_EA     (SM_XS2 + G * FIN * 8)               // MAXE*8 f32 = 6144
#define SM_DST    (SM_EA + MAXE * 8 * 4)               // MAXE int = 768
#define SM_SRCL   (SM_DST + MAXE * 4)                  // MAXE int = 768
#define SM_PTR    (SM_SRCL + MAXE * 4)                 // (G+1) int -> 128
#define SM_W1     (SM_PTR + 128)                       // 64*9 f32 = 2304
#define SM_B1     (SM_W1 + CK * 9 * 4)                 // 64 f32 = 256
#define SM_TOTAL  (SM_B1 + 256)

__global__ void __launch_bounds__(512, 1)
k_fused(const float* __restrict__ x, const float* __restrict__ ea,
        const int* __restrict__ ei, const float* __restrict__ w1,
        const float* __restrict__ b1, const float* __restrict__ w2,
        const float* __restrict__ b2) {
    extern __shared__ char smem[];
    __half2* qbuf  = (__half2*)(smem + SM_QBUF);       // [nl][k][hp]
    float*   w2s   = (float*)(smem + SM_W2);           // [2][8][1024]
    float*   bx    = (float*)(smem + SM_BX);           // [nl][h]
    float2*  xs2   = (float2*)(smem + SM_XS2);         // [nl][f] (v,v)
    float*   ea_s  = (float*)(smem + SM_EA);           // [t][8]
    int*     dst_s = (int*)(smem + SM_DST);
    int*     srcl_s= (int*)(smem + SM_SRCL);
    int*     ptr_s = (int*)(smem + SM_PTR);
    float*   w1s   = (float*)(smem + SM_W1);           // [kl][9] padded
    float*   b1s   = (float*)(smem + SM_B1);

    int tid = threadIdx.x;
    int wid = tid >> 5, lane = tid & 31;
    int n0 = blockIdx.x * G;

    if (tid <= G) ptr_s[tid] = g_ptr[n0 + tid];
    if (tid < G * FIN) {
        int nl = tid >> 4, f = tid & 15;
        float v = x[(n0 + nl) * FIN + f];
        xs2[nl * FIN + f] = make_float2(v, v);
    }
    __syncthreads();

    int P0 = ptr_s[0], P1 = ptr_s[G];
    if (P0 == P1) return;

    // bx[nl][h] = sum_f x[nl,f] * b2[f*64+h]
    for (int i = tid; i < G * HH; i += 512) {
        int nl = i >> 6, h = i & 63;
        float s = 0.f;
#pragma unroll
        for (int f = 0; f < FIN; f++)
            s = fmaf(xs2[nl * FIN + f].x, b2[f * 64 + h], s);
        bx[i] = s;
    }

    uint32_t w2s_base = (uint32_t)__cvta_generic_to_shared(w2s);

    for (int base = P0; base < P1; base += MAXE) {
        int cnt = min(P1 - base, MAXE);
        __syncthreads();
        // edge metadata
        for (int t = tid; t < cnt; t += 512) {
            int e = g_eperm[base + t];
            dst_s[t] = ei[EE + e];
            const float4* p = (const float4*)(ea + (size_t)e * 8);
            float4 u = p[0], v = p[1];
            float* d = ea_s + t * 8;
            d[0]=u.x; d[1]=u.y; d[2]=u.z; d[3]=u.w;
            d[4]=v.x; d[5]=v.y; d[6]=v.z; d[7]=v.w;
            int pos = base + t, sl = 0;
#pragma unroll
            for (int g = 1; g <= G; g++) sl += (pos >= ptr_s[g]);
            srcl_s[t] = sl;
        }
        __syncthreads();

        float a0[JMAX], a1[JMAX];
#pragma unroll
        for (int j = 0; j < JMAX; j++) { a0[j] = 0.f; a1[j] = 0.f; }

        for (int c = 0; c < CHUNKS; c++) {
            // stage w1 slice [kl][f] (pad 9) and b1 slice
            {
                int kl = tid >> 3, f = tid & 7;   // 512 = 64*8
                w1s[kl * 9 + f] = w1[f * KK + c * CK + kl];
                if (tid < CK) b1s[tid] = b1[c * CK + tid];
            }
            // ---- build qbuf for this chunk; w2 tiles double-buffered ----
            // prefetch tile 0
            {
                const float* src = w2 + (size_t)(c * CK) * KK;
#pragma unroll
                for (int i = 0; i < 4; i++)
                    cp16(w2s_base + (tid + i * 512) * 16, src + (tid + i * 512) * 4);
                asm volatile("cp.async.commit_group;");
            }
            int hp = lane;
            int klq = wid & 7;
            int grp = wid >> 3;          // 0/1 -> nl block
#pragma unroll 1
            for (int kt = 0; kt < 8; kt++) {
                if (kt + 1 < 8) {
                    const float* src = w2 + (size_t)(c * CK + (kt + 1) * 8) * KK;
                    uint32_t dst = w2s_base + ((kt + 1) & 1) * 32768;
#pragma unroll
                    for (int i = 0; i < 4; i++)
                        cp16(dst + (tid + i * 512) * 16, src + (tid + i * 512) * 4);
                    asm volatile("cp.async.commit_group;");
                    asm volatile("cp.async.wait_group 1;");
                } else {
                    asm volatile("cp.async.wait_group 0;");
                }
                __syncthreads();

                const float* wrow = w2s + (kt & 1) * 8192 + klq * KK;
                unsigned long long wp[16];
#pragma unroll
                for (int f = 0; f < 16; f++)
                    wp[f] = *(const unsigned long long*)(wrow + f * 64 + hp * 2);

                int kglob = kt * 8 + klq;     // chunk-local k
#pragma unroll
                for (int nl = 0; nl < 8; nl++) {
                    int nn = grp * 8 + nl;
                    unsigned long long acc = 0ULL;
                    const unsigned long long* xp =
                        (const unsigned long long*)(xs2 + nn * FIN);
#pragma unroll
                    for (int f = 0; f < 16; f++)
                        asm("fma.rn.f32x2 %0, %1, %2, %0;"
                            : "+l"(acc) : "l"(xp[f]), "l"(wp[f]));
                    float lo, hi;
                    asm("mov.b64 {%0,%1}, %2;" : "=f"(lo), "=f"(hi) : "l"(acc));
                    qbuf[((size_t)nn * CK + kglob) * 32 + hp] = __floats2half2_rn(lo, hi);
                }
                __syncthreads();
            }

            // ---- dot phase for this chunk ----
#pragma unroll 1
            for (int j = 0; j < JMAX; j++) {
                int t = wid + j * 16;
                if (t >= cnt) break;
                const float* ev = ea_s + t * 8;
                int k0 = lane, k1 = lane + 32;
                float r0 = b1s[k0], r1 = b1s[k1];
#pragma unroll
                for (int f = 0; f < 8; f++) {
                    float e = ev[f];
                    r0 = fmaf(e, w1s[k0 * 9 + f], r0);
                    r1 = fmaf(e, w1s[k1 * 9 + f], r1);
                }
                r0 = fmaxf(r0, 0.f); r1 = fmaxf(r1, 0.f);

                const __half2* qp = qbuf + (size_t)srcl_s[t] * CK * 32 + lane;
                float s0 = 0.f, s1 = 0.f;
#pragma unroll
                for (int kl = 0; kl < 32; kl++) {
                    float rk = __shfl_sync(0xffffffffu, r0, kl);
                    float2 qv = __half22float2(qp[kl * 32]);
                    s0 = fmaf(rk, qv.x, s0);
                    s1 = fmaf(rk, qv.y, s1);
                }
#pragma unroll
                for (int kl = 0; kl < 32; kl++) {
                    float rk = __shfl_sync(0xffffffffu, r1, kl);
                    float2 qv = __half22float2(qp[(kl + 32) * 32]);
                    s0 = fmaf(rk, qv.x, s0);
                    s1 = fmaf(rk, qv.y, s1);
                }
                a0[j] += s0; a1[j] += s1;
            }
            __syncthreads();
        }

        // ---- emit ----
#pragma unroll 1
        for (int j = 0; j < JMAX; j++) {
            int t = wid + j * 16;
            if (t >= cnt) break;
            int dst = dst_s[t], sl = srcl_s[t];
            int h0 = lane * 2;
            atomicAdd(&g_agg[(size_t)dst * 64 + h0],     a0[j] + bx[sl * 64 + h0]);
            atomicAdd(&g_agg[(size_t)dst * 64 + h0 + 1], a1[j] + bx[sl * 64 + h0 + 1]);
        }
    }
}

// ---------------- NNConv epilogue ----------------
__global__ void k_conv(const float* __restrict__ x, const float* __restrict__ rw,
                       const float* __restrict__ cb) {
    int i = blockIdx.x * blockDim.x + threadIdx.x;
    if (i >= NN * HH) return;
    int n = i >> 6, j = i & 63;
    float d = fmaxf((float)g_deg[n], 1.f);
    float v = cb[j] + g_agg[i] / d;
    const float* xv = x + n * 16;
#pragma unroll
    for (int f = 0; f < 16; f++) v = fmaf(xv[f], rw[f * 64 + j], v);
    g_h[i] = fmaxf(v, 0.f);
}

// ---------------- graph layernorm reductions ----------------
__global__ void k_redpart(int which) {
    const float* src = which ? g_h2 : g_h;
    float s = 0.f, q = 0.f;
    for (int i = blockIdx.x * blockDim.x + threadIdx.x; i < NN * HH;
         i += NPART * 256) {
        float v = src[i];
        s += v; q = fmaf(v, v, q);
    }
    __shared__ float bs[256], bq[256];
    bs[threadIdx.x] = s; bq[threadIdx.x] = q;
    __syncthreads();
    for (int off = 128; off; off >>= 1) {
        if (threadIdx.x < off) {
            bs[threadIdx.x] += bs[threadIdx.x + off];
            bq[threadIdx.x] += bq[threadIdx.x + off];
        }
        __syncthreads();
    }
    if (threadIdx.x == 0) { g_psum[blockIdx.x] = bs[0]; g_psumsq[blockIdx.x] = bq[0]; }
}

__global__ void k_redfin(int which) {
    __shared__ double ds[NPART], dq[NPART];
    int t = threadIdx.x;
    ds[t] = (double)g_psum[t];
    dq[t] = (double)g_psumsq[t];
    __syncthreads();
    for (int off = NPART / 2; off; off >>= 1) {
        if (t < off) { ds[t] += ds[t + off]; dq[t] += dq[t + off]; }
        __syncthreads();
    }
    if (t == 0) {
        double M = (double)NN * HH;
        double mu = ds[0] / M;
        double var = dq[0] / M - mu * mu;
        if (var < 0.0) var = 0.0;
        float inv = 1.f / ((float)sqrt(var) + 1e-5f);
        g_stats[2 * which]     = (float)mu;
        g_stats[2 * which + 1] = inv;
    }
}

// ---------------- GAT ----------------
__global__ void k_gatprep(const float* __restrict__ gw, const float* __restrict__ asv,
                          const float* __restrict__ adv, const float* __restrict__ n1w,
                          const float* __restrict__ n1b) {
    int n = blockIdx.x, t = threadIdx.x;
    __shared__ float hs[64];
    float mu = g_stats[0], inv = g_stats[1];
    hs[t] = (g_h[(size_t)n * 64 + t] - mu) * inv * n1w[t] + n1b[t];
    __syncthreads();
    float v = 0.f;
#pragma unroll
    for (int i = 0; i < 64; i++) v = fmaf(hs[i], gw[i * 64 + t], v);
    g_xh[(size_t)n * 64 + t] = v;
    int hd = t >> 4, dd = t & 15;
    float ps = v * asv[t];
    float pd = v * adv[t];
#pragma unroll
    for (int off = 8; off; off >>= 1) {
        ps += __shfl_down_sync(0xffffffffu, ps, off, 16);
        pd += __shfl_down_sync(0xffffffffu, pd, off, 16);
    }
    if (dd == 0) {
        g_asrc[n * 4 + hd] = ps;
        g_adst[n * 4 + hd] = pd;
    }
}

__global__ void k_gat1(const int* __restrict__ ei) {
    int id = blockIdx.x * blockDim.x + threadIdx.x;
    if (id >= E2 * HEADS) return;
    int e2 = id >> 2, hd = id & 3;
    int s, d;
    if (e2 < EE) { s = ei[e2]; d = ei[EE + e2]; }
    else         { s = d = e2 - EE; }
    float a = g_asrc[s * 4 + hd] + g_adst[d * 4 + hd];
    a = (a > 0.f) ? a : 0.2f * a;
    g_alpha[id] = a;
    atomicMaxF(&g_amax[d * 4 + hd], a);
}

__global__ void k_gat2(const int* __restrict__ ei) {
    int id = blockIdx.x * blockDim.x + threadIdx.x;
    if (id >= E2 * HEADS) return;
    int e2 = id >> 2, hd = id & 3;
    int s, d;
    if (e2 < EE) { s = ei[e2]; d = ei[EE + e2]; }
    else         { s = d = e2 - EE; }
    float p = expf(g_alpha[id] - g_amax[d * 4 + hd]);
    atomicAdd(&g_asum[d * 4 + hd], p);
    const float* xs = g_xh + (size_t)s * 64 + hd * 16;
    float* o = g_gout + (size_t)d * 64 + hd * 16;
#pragma unroll
    for (int t = 0; t < 16; t++) atomicAdd(&o[t], p * xs[t]);
}

__global__ void k_gatfin(const float* __restrict__ gb) {
    int i = blockIdx.x * blockDim.x + threadIdx.x;
    if (i >= NN * HH) return;
    int n = i >> 6, j = i & 63;
    float denom = g_asum[n * 4 + (j >> 4)] + 1e-16f;
    g_h2[i] = fmaxf(g_gout[i] / denom + gb[j], 0.f);
}

__global__ void k_pool(const int* __restrict__ batch, const float* __restrict__ n2w,
                       const float* __restrict__ n2b) {
    int i = blockIdx.x * blockDim.x + threadIdx.x;
    if (i >= NN * HH) return;
    int n = i >> 6, j = i & 63;
    float v = (g_h2[i] - g_stats[2]) * g_stats[3] * n2w[j] + n2b[j];
    int g = batch[n];
    atomicAdd(&g_pool[g * 64 + j], v);
    if (j == 0) atomicAdd(&g_gcnt[g], 1);
}

__global__ void k_head(const float* __restrict__ lw, const float* __restrict__ lb,
                       float* __restrict__ out) {
    int g = blockIdx.x, t = threadIdx.x;
    float c = fmaxf((float)g_gcnt[g], 1.f);
    float v = (g_pool[g * 64 + t] / c) * lw[t];
    __shared__ float sm[64];
    sm[t] = v;
    __syncthreads();
    for (int off = 32; off; off >>= 1) {
        if (t < off) sm[t] += sm[t + off];
        __syncthreads();
    }
    if (t == 0) out[g] = sm[0] + lb[0];
}

// ---------------- launch ----------------
extern "C" void kernel_launch(void* const* d_in, const int* in_sizes, int n_in,
                              void* d_out, int out_size) {
    const float* x    = (const float*)d_in[0];
    const int*   ei   = (const int*)d_in[1];
    const float* ea   = (const float*)d_in[2];
    const int*   batch= (const int*)d_in[3];
    const float* enw1 = (const float*)d_in[4];
    const float* enb1 = (const float*)d_in[5];
    const float* enw2 = (const float*)d_in[6];
    const float* enb2 = (const float*)d_in[7];
    const float* rootw= (const float*)d_in[8];
    const float* convb= (const float*)d_in[9];
    const float* n1w  = (const float*)d_in[10];
    const float* n1b  = (const float*)d_in[11];
    const float* gatw = (const float*)d_in[12];
    const float* attS = (const float*)d_in[13];
    const float* attD = (const float*)d_in[14];
    const float* gatb = (const float*)d_in[15];
    const float* n2w  = (const float*)d_in[16];
    const float* n2b  = (const float*)d_in[17];
    const float* linw = (const float*)d_in[18];
    const float* linb = (const float*)d_in[19];
    float* out = (float*)d_out;

    static int smem_set = 0;
    if (!smem_set) {
        cudaFuncSetAttribute(k_fused, cudaFuncAttributeMaxDynamicSharedMemorySize,
                             SM_TOTAL);
        smem_set = 1;
    }

    k_init<<<(NN * HH + 255) / 256, 256>>>();
    k_hist<<<(EE + 255) / 256, 256>>>(ei);
    k_scan<<<1, 1024>>>();
    k_scatter<<<(EE + 255) / 256, 256>>>(ei);

    k_fused<<<NBLK, 512, SM_TOTAL>>>(x, ea, ei, enw1, enb1, enw2, enb2);
    k_conv<<<(NN * HH + 255) / 256, 256>>>(x, rootw, convb);

    k_redpart<<<NPART, 256>>>(0);
    k_redfin<<<1, NPART>>>(0);

    k_gatprep<<<NN, 64>>>(gatw, attS, attD, n1w, n1b);
    k_gat1<<<(E2 * HEADS + 255) / 256, 256>>>(ei);
    k_gat2<<<(E2 * HEADS + 255) / 256, 256>>>(ei);
    k_gatfin<<<(NN * HH + 255) / 256, 256>>>(gatb);

    k_redpart<<<NPART, 256>>>(1);
    k_redfin<<<1, NPART>>>(1);

    k_pool<<<(NN * HH + 255) / 256, 256>>>(batch, n2w, n2b);
    k_head<<<NGRP, 64>>>(linw, linb, out);
}